// round 10
// baseline (speedup 1.0000x reference)
#include <cuda_runtime.h>
#include <cuda_bf16.h>
#include <cstdint>

// GriddingDistance round 10: round-9 pipeline with the point-indexing bug
// fixed (global point index; sample derived from it) + acquire fence after
// the spin-wait.
//   L0a reset counters; L0b memset pred sample0 (8MB exposed)
//   L1  one launch: interleaved [zero pred s1..s7, counter++ when done] and
//       [scatter ALL pred; blocks for sample k spin on counter[k]];
//       gt-half zero blocks at tail bids (hidden under pred scatter).
//   L2  scatter gt.
// Scatter math = round-5 winner (z-window v2/v4 vector REDs).

#define GRID_R 128
#define GSZ    (GRID_R * GRID_R * GRID_R)
#define ZBLK_PER_SAMPLE 128
#define PTS_PER_SBLK    256

__device__ int g_cnt[64];   // per-sample zero-completion counters (pred)

__device__ __forceinline__ void red_add_f32(float* p, float v) {
    atomicAdd(p, v);  // return unused -> REDG
}
__device__ __forceinline__ void red_add_v2_f32(float* p, float a, float b) {
    asm volatile("red.global.add.v2.f32 [%0], {%1, %2};"
                 :: "l"(p), "f"(a), "f"(b) : "memory");
}
__device__ __forceinline__ void red_add_v4_f32(float* p, float a, float b,
                                               float c, float d) {
    asm volatile("red.global.add.v4.f32 [%0], {%1, %2, %3, %4};"
                 :: "l"(p), "f"(a), "f"(b), "f"(c), "f"(d) : "memory");
}

// One block scatters PTS_PER_SBLK consecutive points starting at GLOBAL
// point index 'start' (256 | n_per_sample, so the block is sample-uniform).
__device__ __forceinline__ void scatter_block(const float* __restrict__ pts,
                                              float* __restrict__ cloud_grid,
                                              int n_per_sample,
                                              int start)
{
    int t = start + threadIdx.x;                       // global point index

    float px = fmaf(pts[3 * t + 0], 128.0f, 64.0f);
    float py = fmaf(pts[3 * t + 1], 128.0f, 64.0f);
    float pz = fmaf(pts[3 * t + 2], 128.0f, 64.0f);

    float fx = floorf(px), fy = floorf(py), fz = floorf(pz);
    float dx = px - fx,   dy = py - fy,   dz = pz - fz;
    int ix = (int)fx, iy = (int)fy, iz = (int)fz;

    float wx0 = 1.0f - dx, wy0 = 1.0f - dy, wz0 = 1.0f - dz;
    float w00 = wx0 * wy0, w01 = wx0 * dy, w10 = dx * wy0, w11 = dx * dy;

    int sample = t / n_per_sample;
    float* __restrict__ gb = cloud_grid + (long long)sample * GSZ;

    bool interior = (ix >= 0) & (ix + 1 < GRID_R) &
                    (iy >= 0) & (iy + 1 < GRID_R) &
                    (iz >= 0) & (iz + 1 < GRID_R);

    if (interior) {
        int r00 = (ix * GRID_R + iy) * GRID_R + iz;
        int r01 = r00 + GRID_R;
        int r10 = r00 + GRID_R * GRID_R;
        int r11 = r10 + GRID_R;

        int m4 = iz & 3;
        if ((m4 & 1) == 0) {
            red_add_v2_f32(gb + r00, w00 * wz0, w00 * dz);
            red_add_v2_f32(gb + r01, w01 * wz0, w01 * dz);
            red_add_v2_f32(gb + r10, w10 * wz0, w10 * dz);
            red_add_v2_f32(gb + r11, w11 * wz0, w11 * dz);
        } else if (m4 == 1) {
            red_add_v4_f32(gb + r00 - 1, 0.f, w00 * wz0, w00 * dz, 0.f);
            red_add_v4_f32(gb + r01 - 1, 0.f, w01 * wz0, w01 * dz, 0.f);
            red_add_v4_f32(gb + r10 - 1, 0.f, w10 * wz0, w10 * dz, 0.f);
            red_add_v4_f32(gb + r11 - 1, 0.f, w11 * wz0, w11 * dz, 0.f);
        } else {
            red_add_f32(gb + r00,     w00 * wz0);
            red_add_f32(gb + r00 + 1, w00 * dz);
            red_add_f32(gb + r01,     w01 * wz0);
            red_add_f32(gb + r01 + 1, w01 * dz);
            red_add_f32(gb + r10,     w10 * wz0);
            red_add_f32(gb + r10 + 1, w10 * dz);
            red_add_f32(gb + r11,     w11 * wz0);
            red_add_f32(gb + r11 + 1, w11 * dz);
        }
    } else {
        int ix0 = min(max(ix,     0), GRID_R - 1);
        int ix1 = min(max(ix + 1, 0), GRID_R - 1);
        int iy0 = min(max(iy,     0), GRID_R - 1);
        int iy1 = min(max(iy + 1, 0), GRID_R - 1);
        int iz0 = min(max(iz,     0), GRID_R - 1);
        int iz1 = min(max(iz + 1, 0), GRID_R - 1);
        int rx0 = ix0 * GRID_R * GRID_R, rx1 = ix1 * GRID_R * GRID_R;
        int ry0 = iy0 * GRID_R,          ry1 = iy1 * GRID_R;
        red_add_f32(gb + (rx0 + ry0 + iz0), w00 * wz0);
        red_add_f32(gb + (rx0 + ry0 + iz1), w00 * dz);
        red_add_f32(gb + (rx0 + ry1 + iz0), w01 * wz0);
        red_add_f32(gb + (rx0 + ry1 + iz1), w01 * dz);
        red_add_f32(gb + (rx1 + ry0 + iz0), w10 * wz0);
        red_add_f32(gb + (rx1 + ry0 + iz1), w10 * dz);
        red_add_f32(gb + (rx1 + ry1 + iz0), w11 * wz0);
        red_add_f32(gb + (rx1 + ry1 + iz1), w11 * dz);
    }
}

__global__ void reset_counters()
{
    if (threadIdx.x < 64) g_cnt[threadIdx.x] = 0;
}

// L1: fused pipelined kernel. Bid layout:
//   [0, NZ+NS): Bresenham-interleaved pred-zero (NZ) and pred-scatter (NS)
//   [NZ+NS, NZ+NS+NGZ): gt-half zero (grid-stride)
__global__ __launch_bounds__(256)
void pipeline_kernel(const float* __restrict__ pred,
                     float* __restrict__ out,
                     int n_per_sample,
                     int NZ, int NS, int NGZ,
                     long long grid_per_cloud)
{
    int bid = blockIdx.x;
    int NP  = NZ + NS;

    if (bid < NP) {
        long long lo = (long long)bid       * NZ / NP;
        long long hi = (long long)(bid + 1) * NZ / NP;
        if (hi > lo) {
            // ---- pred-zero block: zb = lo in [0, NZ) ----
            int zb     = (int)lo;
            int sample = 1 + zb / ZBLK_PER_SAMPLE;     // samples 1..b-1
            int chunk  = zb % ZBLK_PER_SAMPLE;
            float* base = out + (long long)sample * GSZ
                              + (long long)chunk * (GSZ / ZBLK_PER_SAMPLE);
            float4* z = (float4*)base;
            const int n4 = GSZ / ZBLK_PER_SAMPLE / 4;  // 4096
            float4 zero = make_float4(0.f, 0.f, 0.f, 0.f);
            #pragma unroll 4
            for (int i = threadIdx.x; i < n4; i += blockDim.x)
                z[i] = zero;
            __syncthreads();
            if (threadIdx.x == 0) {
                __threadfence();                       // release
                atomicAdd(&g_cnt[sample], 1);
            }
        } else {
            // ---- pred-scatter block: sb = bid - lo in [0, NS) ----
            int sb     = bid - (int)lo;
            int start  = sb * PTS_PER_SBLK;            // GLOBAL point index
            int sample = start / n_per_sample;
            if (sample > 0) {                          // sample 0 zeroed by L0
                if (threadIdx.x == 0) {
                    while (atomicAdd(&g_cnt[sample], 0) < ZBLK_PER_SAMPLE)
                        __nanosleep(64);
                    __threadfence();                   // acquire
                }
                __syncthreads();
            }
            scatter_block(pred, out, n_per_sample, start);
        }
    } else {
        // ---- gt-half zero (tail bids; hidden under pred scatter) ----
        int gz = bid - NP;
        float4* z = (float4*)(out + grid_per_cloud);
        long long n4 = grid_per_cloud >> 2;
        long long nthreads = (long long)NGZ * blockDim.x;
        float4 zero = make_float4(0.f, 0.f, 0.f, 0.f);
        for (long long i = (long long)gz * blockDim.x + threadIdx.x;
             i < n4; i += nthreads)
            z[i] = zero;
    }
}

__global__ __launch_bounds__(256)
void scatter_only_kernel(const float* __restrict__ pts,
                         float* __restrict__ g,
                         int n_per_sample,
                         int total_points)
{
    int start = blockIdx.x * PTS_PER_SBLK;
    if (start >= total_points) return;
    scatter_block(pts, g, n_per_sample, start);
}

// Fallback (round-5/8 schedule) for shapes that don't fit the pipeline
__global__ __launch_bounds__(256)
void scatter_and_zero_kernel(const float* __restrict__ pts,
                             float* __restrict__ g,
                             int n_per_sample, int total_points,
                             float* __restrict__ zbase, long long znum)
{
    if (blockIdx.y == 0) {
        int start = blockIdx.x * PTS_PER_SBLK;
        if (start >= total_points) return;
        scatter_block(pts, g, n_per_sample, start);
    } else {
        float4* z = (float4*)zbase;
        long long n4 = znum >> 2;
        long long nthreads = (long long)gridDim.x * blockDim.x;
        float4 zero = make_float4(0.f, 0.f, 0.f, 0.f);
        for (long long i = (long long)blockIdx.x * blockDim.x + threadIdx.x;
             i < n4; i += nthreads)
            z[i] = zero;
    }
}

extern "C" void kernel_launch(void* const* d_in, const int* in_sizes, int n_in,
                              void* d_out, int out_size)
{
    const float* pred = (const float*)d_in[0];
    const float* gt   = (const float*)d_in[1];
    float* out = (float*)d_out;

    int b = out_size / (2 * GSZ);                      // 8
    int total_points = in_sizes[0] / 3;                // 524288
    int n = total_points / b;                          // 65536
    long long grid_per_cloud = (long long)b * GSZ;

    bool pipeline_ok = (b >= 2) && (b <= 65) &&
                       (n % PTS_PER_SBLK == 0) &&
                       (GSZ % (ZBLK_PER_SAMPLE * 4) == 0);

    if (!pipeline_ok) {
        cudaMemsetAsync(out, 0, (size_t)grid_per_cloud * sizeof(float));
        int nblk = (total_points + PTS_PER_SBLK - 1) / PTS_PER_SBLK;
        scatter_and_zero_kernel<<<dim3(nblk, 2), 256>>>(
            pred, out, n, total_points, out + grid_per_cloud, grid_per_cloud);
        scatter_only_kernel<<<nblk, 256>>>(gt, out + grid_per_cloud,
                                           n, total_points);
        return;
    }

    int NZ  = (b - 1) * ZBLK_PER_SAMPLE;               // 896 pred-zero blocks
    int NS  = total_points / PTS_PER_SBLK;             // 2048 pred-scatter blocks
    int NGZ = 1024;                                    // gt-zero blocks

    // L0: reset counters + expose only pred sample0 zero-fill (8MB)
    reset_counters<<<1, 64>>>();
    cudaMemsetAsync(out, 0, (size_t)GSZ * sizeof(float));

    // L1: pipelined pred zero+scatter, gt zero at tail
    pipeline_kernel<<<NZ + NS + NGZ, 256>>>(pred, out, n, NZ, NS, NGZ,
                                            grid_per_cloud);

    // L2: scatter gt
    scatter_only_kernel<<<NS, 256>>>(gt, out + grid_per_cloud, n, total_points);
}

// round 11
// speedup vs baseline: 1.4961x; 1.4961x over previous
#include <cuda_runtime.h>
#include <cuda_bf16.h>
#include <cstdint>

// GriddingDistance round 11: half-split schedule.
//   L0 memset pred samples [0, b/2)              (32MB exposed)
//   L1 scatter pred pts of first half  || zero pred samples [b/2, b)
//   L2 scatter pred pts of second half || zero gt half (64MB)
//   L3 scatter gt (all points)
// Every scatter launch has >= 1024 blocks (small-scatter degradation seen at
// 512 blocks in rounds 7/8 is avoided). Scatter math = round-5 winner.

#define GRID_R 128
#define GSZ    (GRID_R * GRID_R * GRID_R)

__device__ __forceinline__ void red_add_f32(float* p, float v) {
    atomicAdd(p, v);  // return unused -> REDG
}
__device__ __forceinline__ void red_add_v2_f32(float* p, float a, float b) {
    asm volatile("red.global.add.v2.f32 [%0], {%1, %2};"
                 :: "l"(p), "f"(a), "f"(b) : "memory");
}
__device__ __forceinline__ void red_add_v4_f32(float* p, float a, float b,
                                               float c, float d) {
    asm volatile("red.global.add.v4.f32 [%0], {%1, %2, %3, %4};"
                 :: "l"(p), "f"(a), "f"(b), "f"(c), "f"(d) : "memory");
}

__device__ __forceinline__ void scatter_range(const float* __restrict__ pts,
                                              float* __restrict__ g,
                                              int n_per_sample,
                                              int start, int count)
{
    int t = blockIdx.x * blockDim.x + threadIdx.x;
    if (t >= count) return;
    t += start;

    float px = fmaf(pts[3 * t + 0], 128.0f, 64.0f);
    float py = fmaf(pts[3 * t + 1], 128.0f, 64.0f);
    float pz = fmaf(pts[3 * t + 2], 128.0f, 64.0f);

    float fx = floorf(px), fy = floorf(py), fz = floorf(pz);
    float dx = px - fx,   dy = py - fy,   dz = pz - fz;
    int ix = (int)fx, iy = (int)fy, iz = (int)fz;

    float wx0 = 1.0f - dx, wy0 = 1.0f - dy, wz0 = 1.0f - dz;
    float w00 = wx0 * wy0, w01 = wx0 * dy, w10 = dx * wy0, w11 = dx * dy;

    int sample = t / n_per_sample;
    float* __restrict__ gb = g + (long long)sample * GSZ;

    bool interior = (ix >= 0) & (ix + 1 < GRID_R) &
                    (iy >= 0) & (iy + 1 < GRID_R) &
                    (iz >= 0) & (iz + 1 < GRID_R);

    if (interior) {
        int r00 = (ix * GRID_R + iy) * GRID_R + iz;
        int r01 = r00 + GRID_R;
        int r10 = r00 + GRID_R * GRID_R;
        int r11 = r10 + GRID_R;

        int m4 = iz & 3;
        if ((m4 & 1) == 0) {
            red_add_v2_f32(gb + r00, w00 * wz0, w00 * dz);
            red_add_v2_f32(gb + r01, w01 * wz0, w01 * dz);
            red_add_v2_f32(gb + r10, w10 * wz0, w10 * dz);
            red_add_v2_f32(gb + r11, w11 * wz0, w11 * dz);
        } else if (m4 == 1) {
            red_add_v4_f32(gb + r00 - 1, 0.f, w00 * wz0, w00 * dz, 0.f);
            red_add_v4_f32(gb + r01 - 1, 0.f, w01 * wz0, w01 * dz, 0.f);
            red_add_v4_f32(gb + r10 - 1, 0.f, w10 * wz0, w10 * dz, 0.f);
            red_add_v4_f32(gb + r11 - 1, 0.f, w11 * wz0, w11 * dz, 0.f);
        } else {
            red_add_f32(gb + r00,     w00 * wz0);
            red_add_f32(gb + r00 + 1, w00 * dz);
            red_add_f32(gb + r01,     w01 * wz0);
            red_add_f32(gb + r01 + 1, w01 * dz);
            red_add_f32(gb + r10,     w10 * wz0);
            red_add_f32(gb + r10 + 1, w10 * dz);
            red_add_f32(gb + r11,     w11 * wz0);
            red_add_f32(gb + r11 + 1, w11 * dz);
        }
    } else {
        int ix0 = min(max(ix,     0), GRID_R - 1);
        int ix1 = min(max(ix + 1, 0), GRID_R - 1);
        int iy0 = min(max(iy,     0), GRID_R - 1);
        int iy1 = min(max(iy + 1, 0), GRID_R - 1);
        int iz0 = min(max(iz,     0), GRID_R - 1);
        int iz1 = min(max(iz + 1, 0), GRID_R - 1);
        int rx0 = ix0 * GRID_R * GRID_R, rx1 = ix1 * GRID_R * GRID_R;
        int ry0 = iy0 * GRID_R,          ry1 = iy1 * GRID_R;
        red_add_f32(gb + (rx0 + ry0 + iz0), w00 * wz0);
        red_add_f32(gb + (rx0 + ry0 + iz1), w00 * dz);
        red_add_f32(gb + (rx0 + ry1 + iz0), w01 * wz0);
        red_add_f32(gb + (rx0 + ry1 + iz1), w01 * dz);
        red_add_f32(gb + (rx1 + ry0 + iz0), w10 * wz0);
        red_add_f32(gb + (rx1 + ry0 + iz1), w10 * dz);
        red_add_f32(gb + (rx1 + ry1 + iz0), w11 * wz0);
        red_add_f32(gb + (rx1 + ry1 + iz1), w11 * dz);
    }
}

__device__ __forceinline__ void zero_range(float* __restrict__ base,
                                           long long nfloats)
{
    float4* z = (float4*)base;
    long long n4 = nfloats >> 2;
    long long nthreads = (long long)gridDim.x * blockDim.x;
    float4 zero = make_float4(0.f, 0.f, 0.f, 0.f);
    for (long long i = (long long)blockIdx.x * blockDim.x + threadIdx.x;
         i < n4; i += nthreads)
        z[i] = zero;
}

// y==0: scatter pts[start, start+count) into cloud grid g.
// y==1: zero zbase[0, znum) floats.
__global__ __launch_bounds__(256)
void scatter_and_zero_kernel(const float* __restrict__ pts,
                             float* __restrict__ g,
                             int n_per_sample,
                             int start, int count,
                             float* __restrict__ zbase,
                             long long znum)
{
    if (blockIdx.y == 0) {
        scatter_range(pts, g, n_per_sample, start, count);
    } else {
        zero_range(zbase, znum);
    }
}

__global__ __launch_bounds__(256)
void scatter_only_kernel(const float* __restrict__ pts,
                         float* __restrict__ g,
                         int n_per_sample,
                         int start, int count)
{
    scatter_range(pts, g, n_per_sample, start, count);
}

extern "C" void kernel_launch(void* const* d_in, const int* in_sizes, int n_in,
                              void* d_out, int out_size)
{
    const float* pred = (const float*)d_in[0];
    const float* gt   = (const float*)d_in[1];
    float* out = (float*)d_out;

    int b = out_size / (2 * GSZ);                      // 8
    int total_points = in_sizes[0] / 3;                // 524288
    int n = total_points / b;                          // 65536
    long long grid_per_cloud = (long long)b * GSZ;     // 16777216 floats

    if (b < 2) {
        // fallback: round-5 schedule
        cudaMemsetAsync(out, 0, (size_t)grid_per_cloud * sizeof(float));
        int nblk = (total_points + 255) / 256;
        scatter_and_zero_kernel<<<dim3(nblk, 2), 256>>>(
            pred, out, n, 0, total_points,
            out + grid_per_cloud, grid_per_cloud);
        scatter_only_kernel<<<nblk, 256>>>(gt, out + grid_per_cloud,
                                           n, 0, total_points);
        return;
    }

    int sH = b / 2;                                    // first-half samples (4)
    long long zH = (long long)sH * GSZ;                // 32MB of floats
    int ptsH = sH * n;                                 // 262144

    // L0: expose only first-half pred zero-fill (32MB)
    cudaMemsetAsync(out, 0, (size_t)zH * sizeof(float));

    // L1: scatter pred first half || zero pred second half
    int nblk1 = (ptsH + 255) / 256;                    // 1024
    scatter_and_zero_kernel<<<dim3(nblk1, 2), 256>>>(
        pred, out, n, 0, ptsH,
        out + zH, grid_per_cloud - zH);

    // L2: scatter pred second half || zero gt half
    int ptsR = total_points - ptsH;                    // 262144
    int nblk2 = (ptsR + 255) / 256;                    // 1024
    scatter_and_zero_kernel<<<dim3(nblk2, 2), 256>>>(
        pred, out, n, ptsH, ptsR,
        out + grid_per_cloud, grid_per_cloud);

    // L3: scatter gt (grid zeroed in L2, L2-resident)
    int nblk3 = (total_points + 255) / 256;            // 2048
    scatter_only_kernel<<<nblk3, 256>>>(gt, out + grid_per_cloud,
                                        n, 0, total_points);
}